// round 8
// baseline (speedup 1.0000x reference)
#include <cuda_runtime.h>
#include <cstdint>

#define B_   64
#define T_   1024
#define F_   256
#define U_   512
#define G_   1536             // 3*U
#define P_   1024             // 2*U
#define GB_  (G_*B_)          // 98304
#define HB_  (U_*B_)          // 32768 floats per h ping-pong buffer
#define EPS_ 1e-3f

// ---------------------------------------------------------------------------
// Scratch: __device__ globals (allocation-free per harness rules)
// ---------------------------------------------------------------------------
__device__ float g_xwf[(size_t)T_ * G_ * B_];   // [T][G][B]  x@Wf + bi_f
__device__ float g_xwb[(size_t)T_ * G_ * B_];   // [T][G][B]  x@Wb + bi_b
__device__ float g_resid[(size_t)B_ * T_ * P_]; // [B*T][P]   x@Wp
__device__ float g_hf[(size_t)B_ * T_ * U_];    // [B][T][U]
__device__ float g_hb[(size_t)B_ * T_ * U_];    // [B][T][U]
// h ping-pong: [dir][parity], float2 H[kp=256][b=64], element {h[2kp][b], h[2kp+1][b]}
__device__ float g_hbuf[2 * 2 * HB_];
__device__ unsigned g_barc[2];                  // barrier arrive counters
__device__ unsigned g_barg[2];                  // barrier generations

// ---------------------------------------------------------------------------
// f32x2 packed FMA (Blackwell dual-fp32; only reachable via PTX)
// ---------------------------------------------------------------------------
__device__ __forceinline__ void fma2(float2& d, float2 a, float2 b) {
    unsigned long long& dd = reinterpret_cast<unsigned long long&>(d);
    unsigned long long& aa = reinterpret_cast<unsigned long long&>(a);
    unsigned long long& bb = reinterpret_cast<unsigned long long&>(b);
    asm("fma.rn.f32x2 %0, %1, %2, %0;" : "+l"(dd) : "l"(aa), "l"(bb));
}
__device__ __forceinline__ float2 dup2(float x) { return make_float2(x, x); }

// ---------------------------------------------------------------------------
__global__ void init_kernel() {
    int idx = blockIdx.x * blockDim.x + threadIdx.x;
    int stride = gridDim.x * blockDim.x;
    for (int i = idx; i < 2 * 2 * HB_; i += stride) g_hbuf[i] = 0.0f;
    if (idx < 2) { g_barc[idx] = 0u; g_barg[idx] = 0u; }
}

// ---------------------------------------------------------------------------
// GEMM core: 64x64 tile, BK=16, 256 threads.
// ---------------------------------------------------------------------------
__device__ __forceinline__ void gemm_tile(
    const float* __restrict__ A, const float* __restrict__ Bw, int N,
    int row0, int col0, float2 acc[4][2],
    float (*As)[64], float (*Bs)[64])
{
    int tid  = threadIdx.x;
    int tx   = tid & 15;
    int ty   = tid >> 4;
    int lrow = tid >> 2;
    int lkq  = (tid & 3) * 4;
    int lk   = tid >> 4;
    int lnq  = (tid & 15) * 4;

#pragma unroll
    for (int i = 0; i < 4; i++) { acc[i][0] = make_float2(0.f, 0.f); acc[i][1] = make_float2(0.f, 0.f); }

    for (int k0 = 0; k0 < F_; k0 += 16) {
        float4 av = *(const float4*)(A + (size_t)(row0 + lrow) * F_ + k0 + lkq);
        As[lkq + 0][lrow] = av.x;
        As[lkq + 1][lrow] = av.y;
        As[lkq + 2][lrow] = av.z;
        As[lkq + 3][lrow] = av.w;
        *(float4*)(&Bs[lk][lnq]) = *(const float4*)(Bw + (size_t)(k0 + lk) * N + col0 + lnq);
        __syncthreads();

#pragma unroll
        for (int kk = 0; kk < 16; kk++) {
            float4 a4 = *(const float4*)(&As[kk][ty * 4]);
            float4 b4 = *(const float4*)(&Bs[kk][tx * 4]);
            float2 bp0 = make_float2(b4.x, b4.y);
            float2 bp1 = make_float2(b4.z, b4.w);
            float aa[4] = {a4.x, a4.y, a4.z, a4.w};
#pragma unroll
            for (int i = 0; i < 4; i++) {
                float2 ad = dup2(aa[i]);
                fma2(acc[i][0], ad, bp0);
                fma2(acc[i][1], ad, bp1);
            }
        }
        __syncthreads();
    }
}

// Fused xw GEMMs (Wf and Wb): blockIdx.y in [0,48). y<24 -> Wf, else Wb.
__global__ void __launch_bounds__(256) gemm_xw_kernel(
    const float* __restrict__ x,
    const float* __restrict__ Wf, const float* __restrict__ Wb,
    const float* __restrict__ bf, const float* __restrict__ bb)
{
    __shared__ float As[16][64];
    __shared__ float Bs[16][64];
    int ysel = blockIdx.y >= 24;
    const float* Bw   = ysel ? Wb : Wf;
    const float* bias = ysel ? bb : bf;
    float* outp       = ysel ? g_xwb : g_xwf;
    int row0 = blockIdx.x * 64;
    int col0 = (blockIdx.y - (ysel ? 24 : 0)) * 64;

    float2 acc[4][2];
    gemm_tile(x, Bw, G_, row0, col0, acc, As, Bs);

    int tx = threadIdx.x & 15, ty = threadIdx.x >> 4;
#pragma unroll
    for (int i = 0; i < 4; i++) {
        int r = row0 + ty * 4 + i;
        int b = r >> 10;
        int t = r & 1023;
        int c = col0 + tx * 4;
        float v[4] = {acc[i][0].x, acc[i][0].y, acc[i][1].x, acc[i][1].y};
#pragma unroll
        for (int j = 0; j < 4; j++) {
            int g = c + j;
            outp[(size_t)t * GB_ + (size_t)g * B_ + b] = v[j] + bias[g];
        }
    }
}

// Residual projection GEMM (Wp)
__global__ void __launch_bounds__(256) gemm_p_kernel(
    const float* __restrict__ x, const float* __restrict__ Wp)
{
    __shared__ float As[16][64];
    __shared__ float Bs[16][64];
    int row0 = blockIdx.x * 64;
    int col0 = blockIdx.y * 64;

    float2 acc[4][2];
    gemm_tile(x, Wp, P_, row0, col0, acc, As, Bs);

    int tx = threadIdx.x & 15, ty = threadIdx.x >> 4;
#pragma unroll
    for (int i = 0; i < 4; i++) {
        int r = row0 + ty * 4 + i;
        int c = col0 + tx * 4;
        g_resid[(size_t)r * P_ + c + 0] = acc[i][0].x;
        g_resid[(size_t)r * P_ + c + 1] = acc[i][0].y;
        g_resid[(size_t)r * P_ + c + 2] = acc[i][1].x;
        g_resid[(size_t)r * P_ + c + 3] = acc[i][1].y;
    }
}

// ---------------------------------------------------------------------------
// GRU recurrence v8: direction-interleaved to hide barrier turnaround.
// 128 blocks, each owns 4 FORWARD units (jb*4..jb*4+3) AND 4 BACKWARD units.
// Per step: fwd phase (compute+finalize+store+arrive fwd-bar), then bwd phase
// (same for bwd-bar). The WAIT for each barrier sits at the top of that
// direction's next phase, hidden behind the other direction's compute.
// Compute role: 16 warps, warp w -> (kw=w>>1: k-eighth, bh=w&1: batch half);
//   each warp computes partials for all 12 U-cols over its (64k x 32b) tile.
// Finalize role: threads 0..255 -> (uf=tid>>6: unit, b=tid&63).
// SMEM: U fwd+bwd 48KB + partials 24KB = 72KB.
// ---------------------------------------------------------------------------
__global__ void __launch_bounds__(512) gru_kernel(
    const float* __restrict__ Ufm, const float* __restrict__ Ubm,
    const float* __restrict__ bfv, const float* __restrict__ bbv)
{
    extern __shared__ float smem_[];
    float* Usmem[2] = { smem_, smem_ + 12 * 512 };
    float* part = smem_ + 24 * 512;              // [16][12][32]
#define PART(w, c, l) part[(((w) * 12 + (c)) << 5) + (l)]

    int tid = threadIdx.x;
    int jb  = blockIdx.x;      // 0..127

    const float* Umm[2]   = { Ufm, Ubm };
    const float* xws[2]   = { g_xwf, g_xwb };
    float*       houts[2] = { g_hf, g_hb };

    // Load U slices: col c = gate*4+uu -> Um[:, gate*512 + jb*4 + uu]
#pragma unroll
    for (int d = 0; d < 2; d++)
        for (int idx = tid; idx < 12 * 512; idx += 512) {
            int c = idx >> 9;
            int k = idx & 511;
            int g  = c >> 2;
            int uu = c & 3;
            Usmem[d][c * 512 + k] = Umm[d][(size_t)k * G_ + g * U_ + jb * 4 + uu];
        }

    // compute role
    int w    = tid >> 5;
    int lane = tid & 31;
    int kw   = w >> 1;          // k-eighth
    int bh   = w & 1;           // batch half
    int bcol = bh * 32 + lane;
    int ub   = kw * 16;

    // finalize role (threads 0..255)
    bool fin = tid < 256;
    int uf   = tid >> 6;        // 0..3
    int bfin = tid & 63;
    int fug  = jb * 4 + uf;
    float brz[2], brr[2], brh[2];
    if (fin) {
        const float* bv0 = bfv + G_;
        const float* bv1 = bbv + G_;
        brz[0] = bv0[fug]; brr[0] = bv0[U_ + fug]; brh[0] = bv0[2 * U_ + fug];
        brz[1] = bv1[fug]; brr[1] = bv1[U_ + fug]; brh[1] = bv1[2 * U_ + fug];
    }

    __syncthreads();

    for (int s = 0; s < T_; s++) {
        int par = s & 1;
#pragma unroll
        for (int d = 0; d < 2; d++) {
            int tt = d ? (T_ - 1 - s) : s;
            const float2* Hc  = (const float2*)(g_hbuf + ((size_t)d * 2 + par) * HB_);
            float*        HnF = g_hbuf + ((size_t)d * 2 + (par ^ 1)) * HB_;

            // wait for this direction's barrier (released during the other
            // direction's compute phase)
            if (s > 0) {
                if (tid == 0) {
                    volatile unsigned* vg = &g_barg[d];
                    unsigned target = (unsigned)s;
                    while (*vg < target) { __nanosleep(16); }
                    __threadfence();   // acquire + L1D invalidate
                }
                __syncthreads();
            }

            // finalize operand prefetch (independent of dots)
            float xz, xr, xh, hold;
            if (fin) {
                const float* XW = xws[d] + (size_t)tt * GB_;
                xz = XW[(0 * U_ + fug) * B_ + bfin];
                xr = XW[(1 * U_ + fug) * B_ + bfin];
                xh = XW[(2 * U_ + fug) * B_ + bfin];
                float2 hv = Hc[(size_t)(fug >> 1) * 64 + bfin];
                hold = (uf & 1) ? hv.y : hv.x;
            }

            // ---- partial dots: 12 cols over (64 k x own batch) ----
            float2 acc[12];
#pragma unroll
            for (int c = 0; c < 12; c++) acc[c] = make_float2(0.f, 0.f);

            const float2* hpp = Hc + (size_t)(kw * 32) * 64 + bcol;
            const float4* U4  = (const float4*)Usmem[d];

            float2 h0 = hpp[0];
            float2 h1 = hpp[64];
            float2 h2 = hpp[128];
            float2 h3 = hpp[192];
#pragma unroll
            for (int i = 0; i < 16; i += 2) {
                float2 n0, n1, n2, n3;
                if (i < 14) {
                    n0 = hpp[(size_t)(2 * i + 4) * 64];
                    n1 = hpp[(size_t)(2 * i + 5) * 64];
                    n2 = hpp[(size_t)(2 * i + 6) * 64];
                    n3 = hpp[(size_t)(2 * i + 7) * 64];
                }
#pragma unroll
                for (int c = 0; c < 12; c++) {
                    float4 u = U4[c * 128 + ub + i];
                    fma2(acc[c], make_float2(u.x, u.y), h0);
                    fma2(acc[c], make_float2(u.z, u.w), h1);
                }
#pragma unroll
                for (int c = 0; c < 12; c++) {
                    float4 u = U4[c * 128 + ub + i + 1];
                    fma2(acc[c], make_float2(u.x, u.y), h2);
                    fma2(acc[c], make_float2(u.z, u.w), h3);
                }
                h0 = n0; h1 = n1; h2 = n2; h3 = n3;
            }

#pragma unroll
            for (int c = 0; c < 12; c++) PART(w, c, lane) = acc[c].x + acc[c].y;
            __syncthreads();

            // ---- finalize ----
            if (fin) {
                int bh2 = bfin >> 5, ln2 = bfin & 31;
                float sz = 0.f, sr = 0.f, sh = 0.f;
#pragma unroll
                for (int k8 = 0; k8 < 8; k8++) {
                    int wp = 2 * k8 + bh2;
                    sz += PART(wp, 0 * 4 + uf, ln2);
                    sr += PART(wp, 1 * 4 + uf, ln2);
                    sh += PART(wp, 2 * 4 + uf, ln2);
                }
                float z  = 1.0f / (1.0f + expf(-(xz + sz + brz[d])));
                float r  = 1.0f / (1.0f + expf(-(xr + sr + brr[d])));
                float hh = tanhf(xh + r * (sh + brh[d]));
                float hn = z * hold + (1.0f - z) * hh;

                HnF[(((size_t)(fug >> 1) * 64 + bfin) << 1) + (uf & 1)] = hn;
                houts[d][((size_t)bfin * T_ + tt) * U_ + fug] = hn;
            }
            __syncthreads();   // Hn stores complete before release fence

            // arrive (no wait here)
            if (tid == 0) {
                __threadfence();
                unsigned prev = atomicAdd(&g_barc[d], 1u);
                if (prev == 127u) {
                    g_barc[d] = 0u;
                    __threadfence();
                    atomicAdd(&g_barg[d], 1u);
                }
            }
        }
    }
#undef PART
}

// ---------------------------------------------------------------------------
// Epilogue: y = concat(hf,hb) + resid; LayerNorm over last dim (1024)
// ---------------------------------------------------------------------------
__global__ void __launch_bounds__(256) ln_kernel(
    const float* __restrict__ gamma, const float* __restrict__ beta,
    float* __restrict__ out)
{
    __shared__ float red[2][8];
    int row = blockIdx.x;       // b*T + t
    int tid = threadIdx.x;
    int c   = tid * 4;

    const float* hsrc = (tid < 128)
        ? (g_hf + (size_t)row * U_ + c)
        : (g_hb + (size_t)row * U_ + (c - U_));
    float4 h4 = *(const float4*)hsrc;
    float4 r4 = *(const float4*)(g_resid + (size_t)row * P_ + c);

    float y0 = h4.x + r4.x, y1 = h4.y + r4.y, y2 = h4.z + r4.z, y3 = h4.w + r4.w;
    float s  = y0 + y1 + y2 + y3;
    float s2 = y0 * y0 + y1 * y1 + y2 * y2 + y3 * y3;

#pragma unroll
    for (int off = 16; off > 0; off >>= 1) {
        s  += __shfl_xor_sync(0xFFFFFFFFu, s,  off);
        s2 += __shfl_xor_sync(0xFFFFFFFFu, s2, off);
    }
    int wid = tid >> 5, lane = tid & 31;
    if (lane == 0) { red[0][wid] = s; red[1][wid] = s2; }
    __syncthreads();
    s = 0.f; s2 = 0.f;
#pragma unroll
    for (int i = 0; i < 8; i++) { s += red[0][i]; s2 += red[1][i]; }

    float mu  = s * (1.0f / 1024.0f);
    float var = s2 * (1.0f / 1024.0f) - mu * mu;
    float inv = rsqrtf(var + EPS_);

    float4 g4 = *(const float4*)(gamma + c);
    float4 b4 = *(const float4*)(beta + c);
    float4 o;
    o.x = g4.x * (y0 - mu) * inv + b4.x;
    o.y = g4.y * (y1 - mu) * inv + b4.y;
    o.z = g4.z * (y2 - mu) * inv + b4.z;
    o.w = g4.w * (y3 - mu) * inv + b4.w;
    *(float4*)(out + (size_t)row * P_ + c) = o;
}

// ---------------------------------------------------------------------------
extern "C" void kernel_launch(void* const* d_in, const int* in_sizes, int n_in,
                              void* d_out, int out_size) {
    const float* x     = (const float*)d_in[0];
    const float* Wf    = (const float*)d_in[1];
    const float* Uf    = (const float*)d_in[2];
    const float* bf    = (const float*)d_in[3];
    const float* Wb    = (const float*)d_in[4];
    const float* Ub    = (const float*)d_in[5];
    const float* bb    = (const float*)d_in[6];
    const float* Wp    = (const float*)d_in[7];
    const float* gamma = (const float*)d_in[8];
    const float* beta  = (const float*)d_in[9];
    float* out = (float*)d_out;

    const int gru_smem = 24 * 512 * 4 + 16 * 12 * 32 * 4;  // 49152 + 24576 = 73728 B
    cudaFuncSetAttribute(gru_kernel, cudaFuncAttributeMaxDynamicSharedMemorySize, gru_smem);

    init_kernel<<<64, 256>>>();
    gemm_xw_kernel<<<dim3(1024, 48), 256>>>(x, Wf, Wb, bf, bb);
    gemm_p_kernel<<<dim3(1024, 16), 256>>>(x, Wp);
    gru_kernel<<<128, 512, gru_smem>>>(Uf, Ub, bf, bb);
    ln_kernel<<<B_ * T_, 256>>>(gamma, beta, out);
}

// round 9
// speedup vs baseline: 1.2107x; 1.2107x over previous
#include <cuda_runtime.h>
#include <cstdint>

#define B_   64
#define T_   1024
#define F_   256
#define U_   512
#define G_   1536             // 3*U
#define P_   1024             // 2*U
#define GB_  (G_*B_)          // 98304
#define HB_  (U_*B_)          // 32768 floats per h ping-pong buffer
#define EPS_ 1e-3f

// ---------------------------------------------------------------------------
// Scratch: __device__ globals (allocation-free per harness rules)
// ---------------------------------------------------------------------------
__device__ float g_xwf[(size_t)T_ * G_ * B_];   // [T][G][B]  x@Wf + bi_f
__device__ float g_xwb[(size_t)T_ * G_ * B_];   // [T][G][B]  x@Wb + bi_b
__device__ float g_resid[(size_t)B_ * T_ * P_]; // [B*T][P]   x@Wp
__device__ float g_hf[(size_t)B_ * T_ * U_];    // [B][T][U]
__device__ float g_hb[(size_t)B_ * T_ * U_];    // [B][T][U]
// h ping-pong: [dir][parity], float2 H[kp=256][b=64], element {h[2kp][b], h[2kp+1][b]}
__device__ float g_hbuf[2 * 2 * HB_];
__device__ unsigned g_barc[2];                  // barrier arrive counters
__device__ unsigned g_barg[2];                  // barrier generations

// ---------------------------------------------------------------------------
// f32x2 packed FMA (Blackwell dual-fp32; only reachable via PTX)
// ---------------------------------------------------------------------------
__device__ __forceinline__ void fma2(float2& d, float2 a, float2 b) {
    unsigned long long& dd = reinterpret_cast<unsigned long long&>(d);
    unsigned long long& aa = reinterpret_cast<unsigned long long&>(a);
    unsigned long long& bb = reinterpret_cast<unsigned long long&>(b);
    asm("fma.rn.f32x2 %0, %1, %2, %0;" : "+l"(dd) : "l"(aa), "l"(bb));
}
__device__ __forceinline__ float2 dup2(float x) { return make_float2(x, x); }

// ---------------------------------------------------------------------------
__global__ void init_kernel() {
    int idx = blockIdx.x * blockDim.x + threadIdx.x;
    int stride = gridDim.x * blockDim.x;
    for (int i = idx; i < 2 * 2 * HB_; i += stride) g_hbuf[i] = 0.0f;
    if (idx < 2) { g_barc[idx] = 0u; g_barg[idx] = 0u; }
}

// ---------------------------------------------------------------------------
// GEMM core: 64x64 tile, BK=16, 256 threads.
// ---------------------------------------------------------------------------
__device__ __forceinline__ void gemm_tile(
    const float* __restrict__ A, const float* __restrict__ Bw, int N,
    int row0, int col0, float2 acc[4][2],
    float (*As)[64], float (*Bs)[64])
{
    int tid  = threadIdx.x;
    int tx   = tid & 15;
    int ty   = tid >> 4;
    int lrow = tid >> 2;
    int lkq  = (tid & 3) * 4;
    int lk   = tid >> 4;
    int lnq  = (tid & 15) * 4;

#pragma unroll
    for (int i = 0; i < 4; i++) { acc[i][0] = make_float2(0.f, 0.f); acc[i][1] = make_float2(0.f, 0.f); }

    for (int k0 = 0; k0 < F_; k0 += 16) {
        float4 av = *(const float4*)(A + (size_t)(row0 + lrow) * F_ + k0 + lkq);
        As[lkq + 0][lrow] = av.x;
        As[lkq + 1][lrow] = av.y;
        As[lkq + 2][lrow] = av.z;
        As[lkq + 3][lrow] = av.w;
        *(float4*)(&Bs[lk][lnq]) = *(const float4*)(Bw + (size_t)(k0 + lk) * N + col0 + lnq);
        __syncthreads();

#pragma unroll
        for (int kk = 0; kk < 16; kk++) {
            float4 a4 = *(const float4*)(&As[kk][ty * 4]);
            float4 b4 = *(const float4*)(&Bs[kk][tx * 4]);
            float2 bp0 = make_float2(b4.x, b4.y);
            float2 bp1 = make_float2(b4.z, b4.w);
            float aa[4] = {a4.x, a4.y, a4.z, a4.w};
#pragma unroll
            for (int i = 0; i < 4; i++) {
                float2 ad = dup2(aa[i]);
                fma2(acc[i][0], ad, bp0);
                fma2(acc[i][1], ad, bp1);
            }
        }
        __syncthreads();
    }
}

// Fused xw GEMMs (Wf and Wb): blockIdx.y in [0,48). y<24 -> Wf, else Wb.
__global__ void __launch_bounds__(256) gemm_xw_kernel(
    const float* __restrict__ x,
    const float* __restrict__ Wf, const float* __restrict__ Wb,
    const float* __restrict__ bf, const float* __restrict__ bb)
{
    __shared__ float As[16][64];
    __shared__ float Bs[16][64];
    int ysel = blockIdx.y >= 24;
    const float* Bw   = ysel ? Wb : Wf;
    const float* bias = ysel ? bb : bf;
    float* outp       = ysel ? g_xwb : g_xwf;
    int row0 = blockIdx.x * 64;
    int col0 = (blockIdx.y - (ysel ? 24 : 0)) * 64;

    float2 acc[4][2];
    gemm_tile(x, Bw, G_, row0, col0, acc, As, Bs);

    int tx = threadIdx.x & 15, ty = threadIdx.x >> 4;
#pragma unroll
    for (int i = 0; i < 4; i++) {
        int r = row0 + ty * 4 + i;
        int b = r >> 10;
        int t = r & 1023;
        int c = col0 + tx * 4;
        float v[4] = {acc[i][0].x, acc[i][0].y, acc[i][1].x, acc[i][1].y};
#pragma unroll
        for (int j = 0; j < 4; j++) {
            int g = c + j;
            outp[(size_t)t * GB_ + (size_t)g * B_ + b] = v[j] + bias[g];
        }
    }
}

// Residual projection GEMM (Wp)
__global__ void __launch_bounds__(256) gemm_p_kernel(
    const float* __restrict__ x, const float* __restrict__ Wp)
{
    __shared__ float As[16][64];
    __shared__ float Bs[16][64];
    int row0 = blockIdx.x * 64;
    int col0 = blockIdx.y * 64;

    float2 acc[4][2];
    gemm_tile(x, Wp, P_, row0, col0, acc, As, Bs);

    int tx = threadIdx.x & 15, ty = threadIdx.x >> 4;
#pragma unroll
    for (int i = 0; i < 4; i++) {
        int r = row0 + ty * 4 + i;
        int c = col0 + tx * 4;
        g_resid[(size_t)r * P_ + c + 0] = acc[i][0].x;
        g_resid[(size_t)r * P_ + c + 1] = acc[i][0].y;
        g_resid[(size_t)r * P_ + c + 2] = acc[i][1].x;
        g_resid[(size_t)r * P_ + c + 3] = acc[i][1].y;
    }
}

// ---------------------------------------------------------------------------
// GRU recurrence v9: two co-resident blocks per SM, opposite directions.
// 256 blocks x 256 threads (__launch_bounds__(256,2)); bid<128 -> forward,
// else backward; block owns 4 units (jb*4..jb*4+3) of its direction.
// While one block spins on its direction's barrier, the other block's fma
// stream keeps the SM busy (independent chains settle anti-phase).
// Compute: 8 warps, warp w -> (kw=w>>1: k-quarter(128k), bh=w&1: batch half);
//   each warp computes partials for all 12 U-cols over its (128k x 32b) tile.
// Finalize: 256 threads -> (uf=tid>>6: unit, b=tid&63).
// SMEM: U 24KB [12][512] + partials 12KB [8][12][32] = 36KB (x2 blocks = 72KB).
// ---------------------------------------------------------------------------
__global__ void __launch_bounds__(256, 2) gru_kernel(
    const float* __restrict__ Ufm, const float* __restrict__ Ubm,
    const float* __restrict__ bfv, const float* __restrict__ bbv)
{
    extern __shared__ float smem_[];
    float* Us   = smem_;                         // [12][512]
    float* part = smem_ + 12 * 512;              // [8][12][32]
#define PART(w, c, l) part[(((w) * 12 + (c)) << 5) + (l)]

    int tid = threadIdx.x;
    int bid = blockIdx.x;
    int dir = bid >> 7;        // 0..127 fwd, 128..255 bwd
    int jb  = bid & 127;       // unit block: units jb*4 .. jb*4+3

    const float* Um    = dir ? Ubm : Ufm;
    const float* brv   = (dir ? bbv : bfv) + G_;   // recurrent bias b[1]
    const float* xw    = dir ? g_xwb : g_xwf;
    float*       hout  = dir ? g_hb  : g_hf;
    float*       hbase = g_hbuf + (size_t)dir * 2 * HB_;

    // Load U slice: col c = gate*4+uu -> Um[:, gate*512 + jb*4 + uu]
    for (int idx = tid; idx < 12 * 512; idx += 256) {
        int c = idx >> 9;
        int k = idx & 511;
        int g  = c >> 2;
        int uu = c & 3;
        Us[c * 512 + k] = Um[(size_t)k * G_ + g * U_ + jb * 4 + uu];
    }

    // compute role
    int w    = tid >> 5;        // 0..7
    int lane = tid & 31;
    int kw   = w >> 1;          // k-quarter: k in [kw*128, kw*128+128)
    int bh   = w & 1;           // batch half
    int bcol = bh * 32 + lane;
    int ub   = kw * 32;         // float4 index offset within a col row

    // finalize role
    int uf   = tid >> 6;        // 0..3
    int bfin = tid & 63;
    int fug  = jb * 4 + uf;
    float brz = brv[fug];
    float brr = brv[U_ + fug];
    float brh = brv[2 * U_ + fug];

    const float4* U4 = (const float4*)Us;   // index: c*128 + ub + i

    __syncthreads();

    for (int s = 0; s < T_; s++) {
        int tt = dir ? (T_ - 1 - s) : s;
        int par = s & 1;
        const float2* Hc  = (const float2*)(hbase + (size_t)par * HB_);   // [256][64]
        float*        HnF = hbase + (size_t)(par ^ 1) * HB_;

        // wait for this direction's previous step to be globally visible
        if (s > 0) {
            if (tid == 0) {
                volatile unsigned* vg = &g_barg[dir];
                unsigned target = (unsigned)s;
                while (*vg < target) { __nanosleep(16); }
                __threadfence();   // acquire + L1D invalidate
            }
            __syncthreads();
        }

        // finalize operand prefetch (independent of dots)
        const float* XW = xw + (size_t)tt * GB_;
        float xz = XW[(0 * U_ + fug) * B_ + bfin];
        float xr = XW[(1 * U_ + fug) * B_ + bfin];
        float xh = XW[(2 * U_ + fug) * B_ + bfin];
        float2 hv = Hc[(size_t)(fug >> 1) * 64 + bfin];
        float hold = (uf & 1) ? hv.y : hv.x;

        // ---- partial dots: 12 cols over (128 k x own batch half) ----
        float2 acc[12];
#pragma unroll
        for (int c = 0; c < 12; c++) acc[c] = make_float2(0.f, 0.f);

        const float2* hpp = Hc + (size_t)(kw * 64) * 64 + bcol;

        float2 h0 = hpp[0];
        float2 h1 = hpp[64];
        float2 h2 = hpp[128];
        float2 h3 = hpp[192];
#pragma unroll
        for (int i = 0; i < 32; i += 2) {
            float2 n0, n1, n2, n3;
            if (i < 30) {
                n0 = hpp[(size_t)(2 * i + 4) * 64];
                n1 = hpp[(size_t)(2 * i + 5) * 64];
                n2 = hpp[(size_t)(2 * i + 6) * 64];
                n3 = hpp[(size_t)(2 * i + 7) * 64];
            }
#pragma unroll
            for (int c = 0; c < 12; c++) {
                float4 u = U4[c * 128 + ub + i];
                fma2(acc[c], make_float2(u.x, u.y), h0);
                fma2(acc[c], make_float2(u.z, u.w), h1);
            }
#pragma unroll
            for (int c = 0; c < 12; c++) {
                float4 u = U4[c * 128 + ub + i + 1];
                fma2(acc[c], make_float2(u.x, u.y), h2);
                fma2(acc[c], make_float2(u.z, u.w), h3);
            }
            h0 = n0; h1 = n1; h2 = n2; h3 = n3;
        }

#pragma unroll
        for (int c = 0; c < 12; c++) PART(w, c, lane) = acc[c].x + acc[c].y;
        __syncthreads();

        // ---- finalize: thread -> (unit uf, batch bfin) ----
        {
            int bh2 = bfin >> 5, ln2 = bfin & 31;
            float sz = 0.f, sr = 0.f, sh = 0.f;
#pragma unroll
            for (int kq = 0; kq < 4; kq++) {
                int wp = 2 * kq + bh2;
                sz += PART(wp, 0 * 4 + uf, ln2);
                sr += PART(wp, 1 * 4 + uf, ln2);
                sh += PART(wp, 2 * 4 + uf, ln2);
            }
            float z  = 1.0f / (1.0f + expf(-(xz + sz + brz)));
            float r  = 1.0f / (1.0f + expf(-(xr + sr + brr)));
            float hh = tanhf(xh + r * (sh + brh));
            float hn = z * hold + (1.0f - z) * hh;

            HnF[(((size_t)(fug >> 1) * 64 + bfin) << 1) + (uf & 1)] = hn;
            __syncthreads();   // all Hn stores complete before release

            // arrive (no wait here — wait is at top of next step)
            if (tid == 0) {
                __threadfence();
                unsigned prev = atomicAdd(&g_barc[dir], 1u);
                if (prev == 127u) {
                    g_barc[dir] = 0u;
                    __threadfence();
                    atomicAdd(&g_barg[dir], 1u);
                }
            }
            // scattered per-timestep output store (overlaps barrier latency)
            hout[((size_t)bfin * T_ + tt) * U_ + fug] = hn;
        }
    }
#undef PART
}

// ---------------------------------------------------------------------------
// Epilogue: y = concat(hf,hb) + resid; LayerNorm over last dim (1024)
// ---------------------------------------------------------------------------
__global__ void __launch_bounds__(256) ln_kernel(
    const float* __restrict__ gamma, const float* __restrict__ beta,
    float* __restrict__ out)
{
    __shared__ float red[2][8];
    int row = blockIdx.x;       // b*T + t
    int tid = threadIdx.x;
    int c   = tid * 4;

    const float* hsrc = (tid < 128)
        ? (g_hf + (size_t)row * U_ + c)
        : (g_hb + (size_t)row * U_ + (c - U_));
    float4 h4 = *(const float4*)hsrc;
    float4 r4 = *(const float4*)(g_resid + (size_t)row * P_ + c);

    float y0 = h4.x + r4.x, y1 = h4.y + r4.y, y2 = h4.z + r4.z, y3 = h4.w + r4.w;
    float s  = y0 + y1 + y2 + y3;
    float s2 = y0 * y0 + y1 * y1 + y2 * y2 + y3 * y3;

#pragma unroll
    for (int off = 16; off > 0; off >>= 1) {
        s  += __shfl_xor_sync(0xFFFFFFFFu, s,  off);
        s2 += __shfl_xor_sync(0xFFFFFFFFu, s2, off);
    }
    int wid = tid >> 5, lane = tid & 31;
    if (lane == 0) { red[0][wid] = s; red[1][wid] = s2; }
    __syncthreads();
    s = 0.f; s2 = 0.f;
#pragma unroll
    for (int i = 0; i < 8; i++) { s += red[0][i]; s2 += red[1][i]; }

    float mu  = s * (1.0f / 1024.0f);
    float var = s2 * (1.0f / 1024.0f) - mu * mu;
    float inv = rsqrtf(var + EPS_);

    float4 g4 = *(const float4*)(gamma + c);
    float4 b4 = *(const float4*)(beta + c);
    float4 o;
    o.x = g4.x * (y0 - mu) * inv + b4.x;
    o.y = g4.y * (y1 - mu) * inv + b4.y;
    o.z = g4.z * (y2 - mu) * inv + b4.z;
    o.w = g4.w * (y3 - mu) * inv + b4.w;
    *(float4*)(out + (size_t)row * P_ + c) = o;
}

// ---------------------------------------------------------------------------
extern "C" void kernel_launch(void* const* d_in, const int* in_sizes, int n_in,
                              void* d_out, int out_size) {
    const float* x     = (const float*)d_in[0];
    const float* Wf    = (const float*)d_in[1];
    const float* Uf    = (const float*)d_in[2];
    const float* bf    = (const float*)d_in[3];
    const float* Wb    = (const float*)d_in[4];
    const float* Ub    = (const float*)d_in[5];
    const float* bb    = (const float*)d_in[6];
    const float* Wp    = (const float*)d_in[7];
    const float* gamma = (const float*)d_in[8];
    const float* beta  = (const float*)d_in[9];
    float* out = (float*)d_out;

    const int gru_smem = 12 * 512 * 4 + 8 * 12 * 32 * 4;  // 24576 + 12288 = 36864 B
    cudaFuncSetAttribute(gru_kernel, cudaFuncAttributeMaxDynamicSharedMemorySize, gru_smem);

    init_kernel<<<64, 256>>>();
    gemm_xw_kernel<<<dim3(1024, 48), 256>>>(x, Wf, Wb, bf, bb);
    gemm_p_kernel<<<dim3(1024, 16), 256>>>(x, Wp);
    gru_kernel<<<256, 256, gru_smem>>>(Uf, Ub, bf, bb);
    ln_kernel<<<B_ * T_, 256>>>(gamma, beta, out);
}